// round 9
// baseline (speedup 1.0000x reference)
#include <cuda_runtime.h>
#include <cuda_fp16.h>
#include <cstdint>

// ----------------------------------------------------------------------------
// message_pass: out = prelu(prelu([x_i|x_j|edge] @ W1 + b1) @ W2 + b2)
// E=500000, C=64, CE=16, d_in=144, HID=128
//
// Two-kernel, NON-persistent design (risk reduction after R8 timeout):
//   1) convert_weights_kernel: fp32 W1/W2 -> padded fp16 layout in __device__
//      scratch (one small launch).
//   2) message_pass_kernel: one 128-row tile per CTA (grid=3907), occupancy 2.
//      Each CTA float4-copies the 56 KB fp16 weight image smem<-scratch,
//      then runs the fused mma.sync pipeline (warp-private 16-row stripe,
//      GEMM1 -> bias+PReLU in regs -> GEMM2 -> bias+PReLU -> gmem).
// ----------------------------------------------------------------------------

#define C_DIM   64
#define CE_DIM  16
#define DIN     144
#define HID     128
#define TILE_M  128

// fp16 row strides in bytes (odd 16B units => conflict-free LDS/ldmatrix)
#define W1_STRIDE 304   // 152 fp16 (144 used)
#define W2_STRIDE 272   // 136 fp16 (128 used)
#define A_STRIDE  304

// weight image layout (same in scratch and smem)
#define OFF_W1 0                     // 128 * 304 = 38912
#define OFF_W2 38912                 // 64 * 272  = 17408
#define WBYTES 56320                 // W1 + W2 image
// smem-only regions
#define OFF_B1 56320                 // 128 floats
#define OFF_B2 56832                 // 64 floats
#define OFF_A  57088                 // 8 warps * 16 rows * 304 = 38912
#define SMEM_TOTAL 96000

__device__ __align__(16) unsigned char g_wh[WBYTES];   // fp16 weight scratch

// ---------------------------------------------------------------- helpers
__device__ __forceinline__ uint32_t smem_u32(const void* p) {
    uint32_t a;
    asm("{ .reg .u64 t; cvta.to.shared.u64 t, %1; cvt.u32.u64 %0, t; }" : "=r"(a) : "l"(p));
    return a;
}

__device__ __forceinline__ uint32_t pk(float lo, float hi) {
    __half2 h = __floats2half2_rn(lo, hi);   // .x = lo (even col), .y = hi
    return *reinterpret_cast<uint32_t*>(&h);
}

__device__ __forceinline__ void mma16816(float* d, const uint32_t* a,
                                         uint32_t b0, uint32_t b1) {
    asm volatile(
        "mma.sync.aligned.m16n8k16.row.col.f32.f16.f16.f32 "
        "{%0,%1,%2,%3}, {%4,%5,%6,%7}, {%8,%9}, {%0,%1,%2,%3};"
        : "+f"(d[0]), "+f"(d[1]), "+f"(d[2]), "+f"(d[3])
        : "r"(a[0]), "r"(a[1]), "r"(a[2]), "r"(a[3]), "r"(b0), "r"(b1));
}

// A fragment via ldmatrix.x4 from the warp's 16-row stripe.
// lanes 0-7: rows0-7/k0-7, 8-15: rows8-15/k0-7, 16-23: rows0-7/k8-15, 24-31: rows8-15/k8-15
__device__ __forceinline__ void lda(uint32_t* a, uint32_t abase, int lane, int kt) {
    int m = lane >> 3;
    uint32_t addr = abase
                  + (uint32_t)((lane & 7) + 8 * (m & 1)) * A_STRIDE
                  + (uint32_t)(16 * (m >> 1))
                  + (uint32_t)(kt * 32);
    asm volatile("ldmatrix.sync.aligned.m8n8.x4.shared.b16 {%0,%1,%2,%3}, [%4];"
        : "=r"(a[0]), "=r"(a[1]), "=r"(a[2]), "=r"(a[3]) : "r"(addr));
}

// B fragment (col-major k16n8) from W^T [n][k] rows: thread t holds
// {B[k0][n],B[k0+1][n]}, k0=(t%4)*2, n=t/4; second reg at k0+8 (+16 B).
// 304/272-byte strides => 8 row-groups land on 8 distinct 16B bank regions.
__device__ __forceinline__ void ldb(uint32_t& b0, uint32_t& b1, uint32_t addr) {
    asm volatile("ld.shared.b32 %0, [%2];\n\tld.shared.b32 %1, [%2+16];"
        : "=r"(b0), "=r"(b1) : "r"(addr));
}

// ---------------------------------------------------------------- tile I/O
// Per-warp row gather: 2 lanes per row; 18 float4 per lane.
__device__ __forceinline__ void ldg_tile(float4* v, int t, int E, int w, int lane,
                                         const float* __restrict__ xi,
                                         const float* __restrict__ xj,
                                         const float* __restrict__ ea) {
    int row = t * TILE_M + w * 16 + (lane >> 1);
    size_t rc = (size_t)(row < E ? row : E - 1);
    int half = lane & 1;
    const float4* pi = (const float4*)(xi + rc * C_DIM) + half * 8;
    const float4* pj = (const float4*)(xj + rc * C_DIM) + half * 8;
    const float4* pe = (const float4*)(ea + rc * CE_DIM) + half * 2;
    #pragma unroll
    for (int i = 0; i < 8; i++) v[i] = pi[i];
    #pragma unroll
    for (int i = 0; i < 8; i++) v[8 + i] = pj[i];
    v[16] = pe[0];
    v[17] = pe[1];
}

// fp32->fp16 convert + store warp's 16-row stripe.
// Row cols: [0:64)=x_i, [64:128)=x_j, [128:144)=edge.
__device__ __forceinline__ void sts_tile(const float4* v, uint32_t abase, int lane) {
    uint32_t r = abase + (uint32_t)(lane >> 1) * A_STRIDE + (uint32_t)(lane & 1) * 64;
    #pragma unroll
    for (int i = 0; i < 8; i++) {
        uint32_t lo = pk(v[i].x, v[i].y), hi = pk(v[i].z, v[i].w);
        asm volatile("st.shared.v2.b32 [%0], {%1,%2};" :: "r"(r + i * 8), "r"(lo), "r"(hi));
    }
    #pragma unroll
    for (int i = 0; i < 8; i++) {
        uint32_t lo = pk(v[8 + i].x, v[8 + i].y), hi = pk(v[8 + i].z, v[8 + i].w);
        asm volatile("st.shared.v2.b32 [%0], {%1,%2};" :: "r"(r + 128 + i * 8), "r"(lo), "r"(hi));
    }
    uint32_t re = abase + (uint32_t)(lane >> 1) * A_STRIDE + 256 + (uint32_t)(lane & 1) * 16;
    #pragma unroll
    for (int i = 0; i < 2; i++) {
        uint32_t lo = pk(v[16 + i].x, v[16 + i].y), hi = pk(v[16 + i].z, v[16 + i].w);
        asm volatile("st.shared.v2.b32 [%0], {%1,%2};" :: "r"(re + i * 8), "r"(lo), "r"(hi));
    }
}

// ---------------------------------------------------------------- setup kernel
// fp32 W1[k][n] / W2[k][n] -> fp16 W^T padded image in g_wh. One elem/thread.
__global__ void convert_weights_kernel(const float* __restrict__ W1,
                                       const float* __restrict__ W2) {
    int idx = blockIdx.x * blockDim.x + threadIdx.x;
    if (idx < DIN * HID) {
        int k = idx >> 7, n = idx & 127;
        *(__half*)(g_wh + OFF_W1 + n * W1_STRIDE + k * 2) = __float2half(W1[idx]);
    } else {
        int j = idx - DIN * HID;
        if (j < HID * C_DIM) {
            int k = j >> 6, n = j & 63;
            *(__half*)(g_wh + OFF_W2 + n * W2_STRIDE + k * 2) = __float2half(W2[j]);
        }
    }
}

// ---------------------------------------------------------------- main kernel
__global__ void __launch_bounds__(256, 2)
message_pass_kernel(const float* __restrict__ x_i,
                    const float* __restrict__ x_j,
                    const float* __restrict__ edge_attr,
                    const float* __restrict__ b1,
                    const float* __restrict__ b2,
                    const float* __restrict__ alphaP,
                    float* __restrict__ out,
                    int E) {
    extern __shared__ char smem[];
    const uint32_t sb = smem_u32(smem);
    const int tid = threadIdx.x;
    const int lane = tid & 31;
    const int w = tid >> 5;
    const int t = (int)blockIdx.x;

    // issue my tile's gmem loads first (overlap the weight copy)
    float4 v[18];
    ldg_tile(v, t, E, w, lane, x_i, x_j, edge_attr);

    // copy ready fp16 weight image scratch -> smem (56 KB, float4)
    {
        const float4* src = (const float4*)g_wh;
        float4* dst = (float4*)smem;
        for (int i = tid; i < WBYTES / 16; i += 256) dst[i] = src[i];
    }
    float* b1s = (float*)(smem + OFF_B1);
    float* b2s = (float*)(smem + OFF_B2);
    if (tid < HID)   b1s[tid] = b1[tid];
    if (tid < C_DIM) b2s[tid] = b2[tid];
    const float alpha = alphaP[0];
    __syncthreads();

    // stage my 16-row stripe (warp-private)
    const uint32_t abase = sb + OFF_A + (uint32_t)w * 16 * A_STRIDE;
    sts_tile(v, abase, lane);
    __syncwarp();

    const uint32_t w1b = sb + OFF_W1 + (uint32_t)(lane >> 2) * W1_STRIDE + (uint32_t)(lane & 3) * 4;
    const uint32_t w2b = sb + OFF_W2 + (uint32_t)(lane >> 2) * W2_STRIDE + (uint32_t)(lane & 3) * 4;
    const int cq = (lane & 3) * 2;

    // ---- GEMM1: [16 x 144] @ W1^T -> [16 x 128]   (9 k-steps, 16 n-tiles)
    float acc1[16][4];
    #pragma unroll
    for (int nt = 0; nt < 16; nt++)
        #pragma unroll
        for (int j = 0; j < 4; j++) acc1[nt][j] = 0.0f;

    for (int kt = 0; kt < 9; kt++) {
        uint32_t a[4];
        lda(a, abase, lane, kt);
        #pragma unroll
        for (int nt = 0; nt < 16; nt++) {
            uint32_t b0, b1r;
            ldb(b0, b1r, w1b + (uint32_t)(nt * 8) * W1_STRIDE + (uint32_t)(kt * 32));
            mma16816(acc1[nt], a, b0, b1r);
        }
    }

    // ---- epilogue1: h = prelu(acc1 + b1) -> fp16 A-fragments for GEMM2
    // (acc layout == A-frag layout: af[p] covers hidden cols 16p..16p+15)
    uint32_t af[8][4];
    #pragma unroll
    for (int p = 0; p < 8; p++) {
        #pragma unroll
        for (int hh = 0; hh < 2; hh++) {
            int nt = 2 * p + hh;
            float bb0 = b1s[8 * nt + cq], bb1 = b1s[8 * nt + cq + 1];
            float h0 = acc1[nt][0] + bb0; h0 = (h0 >= 0.0f) ? h0 : alpha * h0;
            float h1 = acc1[nt][1] + bb1; h1 = (h1 >= 0.0f) ? h1 : alpha * h1;
            float h2 = acc1[nt][2] + bb0; h2 = (h2 >= 0.0f) ? h2 : alpha * h2;
            float h3 = acc1[nt][3] + bb1; h3 = (h3 >= 0.0f) ? h3 : alpha * h3;
            af[p][2 * hh + 0] = pk(h0, h1);   // rows lane/4
            af[p][2 * hh + 1] = pk(h2, h3);   // rows lane/4 + 8
        }
    }

    // ---- GEMM2: [16 x 128] @ W2^T -> [16 x 64]   (8 k-steps, 8 n-tiles)
    float acc2[8][4];
    #pragma unroll
    for (int nt = 0; nt < 8; nt++)
        #pragma unroll
        for (int j = 0; j < 4; j++) acc2[nt][j] = 0.0f;

    #pragma unroll
    for (int kt2 = 0; kt2 < 8; kt2++) {
        #pragma unroll
        for (int nt2 = 0; nt2 < 8; nt2++) {
            uint32_t b0, b1r;
            ldb(b0, b1r, w2b + (uint32_t)(nt2 * 8) * W2_STRIDE + (uint32_t)(kt2 * 32));
            mma16816(acc2[nt2], af[kt2], b0, b1r);
        }
    }

    // ---- epilogue2: out = prelu(acc2 + b2), float2 stores
    {
        int r0 = t * TILE_M + w * 16 + (lane >> 2);
        #pragma unroll
        for (int nt2 = 0; nt2 < 8; nt2++) {
            int c = 8 * nt2 + cq;
            float bb0 = b2s[c], bb1 = b2s[c + 1];
            float o0 = acc2[nt2][0] + bb0; o0 = (o0 >= 0.0f) ? o0 : alpha * o0;
            float o1 = acc2[nt2][1] + bb1; o1 = (o1 >= 0.0f) ? o1 : alpha * o1;
            float o2 = acc2[nt2][2] + bb0; o2 = (o2 >= 0.0f) ? o2 : alpha * o2;
            float o3 = acc2[nt2][3] + bb1; o3 = (o3 >= 0.0f) ? o3 : alpha * o3;
            if (r0 < E)
                *(float2*)(out + (size_t)r0 * C_DIM + c) = make_float2(o0, o1);
            if (r0 + 8 < E)
                *(float2*)(out + (size_t)(r0 + 8) * C_DIM + c) = make_float2(o2, o3);
        }
    }
}

// ---------------------------------------------------------------- launch
extern "C" void kernel_launch(void* const* d_in, const int* in_sizes, int n_in,
                              void* d_out, int out_size) {
    const float* x_i    = (const float*)d_in[0];
    const float* x_j    = (const float*)d_in[1];
    const float* edge_a = (const float*)d_in[2];
    const float* W1     = (const float*)d_in[3];
    const float* b1     = (const float*)d_in[4];
    const float* W2     = (const float*)d_in[5];
    const float* b2     = (const float*)d_in[6];
    const float* alphaP = (const float*)d_in[7];
    float* out = (float*)d_out;

    int E = in_sizes[0] / C_DIM;
    int ntiles = (E + TILE_M - 1) / TILE_M;
    if (ntiles < 1) ntiles = 1;

    // 1) convert weights into fp16 scratch (26624 elements, 1/thread)
    convert_weights_kernel<<<(DIN * HID + HID * C_DIM + 255) / 256, 256>>>(W1, W2);

    // 2) main fused MLP, one 128-row tile per CTA
    cudaFuncSetAttribute(message_pass_kernel,
                         cudaFuncAttributeMaxDynamicSharedMemorySize, SMEM_TOTAL);
    message_pass_kernel<<<ntiles, 256, SMEM_TOTAL>>>(
        x_i, x_j, edge_a, b1, b2, alphaP, out, E);
}

// round 15
// speedup vs baseline: 1.0115x; 1.0115x over previous
#include <cuda_runtime.h>
#include <cuda_fp16.h>
#include <cstdint>

// ----------------------------------------------------------------------------
// message_pass: out = prelu(prelu([x_i|x_j|edge] @ W1 + b1) @ W2 + b2)
// E=500000, C=64, CE=16, d_in=144, HID=128
//
// R15 == R11..R14 (never ran): R9 structure + ldmatrix.x4.trans B loads
// with corrected [k][n] weight layout (rows = k, n contiguous; padded strides
// 272/144 B => 8 k-row addresses on 8 distinct 16B bank regions).
// trans-ldmatrix yields the exact col-major B fragment:
//   frag(l) = {S[2(l%4)][l/4], S[2(l%4)+1][l/4]} = {B[k0][n], B[k0+1][n]}.
// 1 instruction / 2 n-tiles instead of 2 scalar LDS per mma (R9 baseline).
// ----------------------------------------------------------------------------

#define C_DIM   64
#define CE_DIM  16
#define DIN     144
#define HID     128
#define TILE_M  128

// strides in bytes
#define W1_STRIDE 272   // 128 fp16 used, padded to 136 (odd 16B units)
#define W2_STRIDE 144   // 64 fp16 used, padded to 72
#define A_STRIDE  304   // 144 fp16 used, padded to 152 (R9-validated)

// weight image layout (same in scratch and smem): rows = k, cols = n
#define OFF_W1 0                     // 144 * 272 = 39168
#define OFF_W2 39168                 // 128 * 144 = 18432
#define WBYTES 57600
// smem-only regions
#define OFF_B1 57600                 // 128 floats
#define OFF_B2 58112                 // 64 floats
#define OFF_A  58368                 // 8 warps * 16 rows * 304 = 38912
#define SMEM_TOTAL 97280

__device__ __align__(16) unsigned char g_wh[WBYTES];   // fp16 weight scratch

// ---------------------------------------------------------------- helpers
__device__ __forceinline__ uint32_t smem_u32(const void* p) {
    uint32_t a;
    asm("{ .reg .u64 t; cvta.to.shared.u64 t, %1; cvt.u32.u64 %0, t; }" : "=r"(a) : "l"(p));
    return a;
}

__device__ __forceinline__ uint32_t pk(float lo, float hi) {
    __half2 h = __floats2half2_rn(lo, hi);
    return *reinterpret_cast<uint32_t*>(&h);
}

__device__ __forceinline__ void mma16816(float* d, const uint32_t* a,
                                         uint32_t b0, uint32_t b1) {
    asm volatile(
        "mma.sync.aligned.m16n8k16.row.col.f32.f16.f16.f32 "
        "{%0,%1,%2,%3}, {%4,%5,%6,%7}, {%8,%9}, {%0,%1,%2,%3};"
        : "+f"(d[0]), "+f"(d[1]), "+f"(d[2]), "+f"(d[3])
        : "r"(a[0]), "r"(a[1]), "r"(a[2]), "r"(a[3]), "r"(b0), "r"(b1));
}

// A fragment via ldmatrix.x4 (non-trans) from the warp's 16-row stripe.
// (HW-validated in the 188.5us R9 pass.)
__device__ __forceinline__ void lda(uint32_t* a, uint32_t abase, int lane, int kt) {
    int m = lane >> 3;
    uint32_t addr = abase
                  + (uint32_t)((lane & 7) + 8 * (m & 1)) * A_STRIDE
                  + (uint32_t)(16 * (m >> 1))
                  + (uint32_t)(kt * 32);
    asm volatile("ldmatrix.sync.aligned.m8n8.x4.shared.b16 {%0,%1,%2,%3}, [%4];"
        : "=r"(a[0]), "=r"(a[1]), "=r"(a[2]), "=r"(a[3]) : "r"(addr));
}

// B fragments via ldmatrix.x4.trans from [k][n] storage (rows = k):
//   m0=(k0-7,n0-7)->b0 of n-tile 2q   m1=(k8-15,n0-7)->b1 of n-tile 2q
//   m2=(k0-7,n8-15)->b0 of 2q+1      m3=(k8-15,n8-15)->b1 of 2q+1
__device__ __forceinline__ void ldb4(uint32_t* b, uint32_t addr) {
    asm volatile("ldmatrix.sync.aligned.m8n8.x4.trans.shared.b16 {%0,%1,%2,%3}, [%4];"
        : "=r"(b[0]), "=r"(b[1]), "=r"(b[2]), "=r"(b[3]) : "r"(addr));
}

// ---------------------------------------------------------------- tile I/O
__device__ __forceinline__ void ldg_tile(float4* v, int t, int E, int w, int lane,
                                         const float* __restrict__ xi,
                                         const float* __restrict__ xj,
                                         const float* __restrict__ ea) {
    int row = t * TILE_M + w * 16 + (lane >> 1);
    size_t rc = (size_t)(row < E ? row : E - 1);
    int half = lane & 1;
    const float4* pi = (const float4*)(xi + rc * C_DIM) + half * 8;
    const float4* pj = (const float4*)(xj + rc * C_DIM) + half * 8;
    const float4* pe = (const float4*)(ea + rc * CE_DIM) + half * 2;
    #pragma unroll
    for (int i = 0; i < 8; i++) v[i] = pi[i];
    #pragma unroll
    for (int i = 0; i < 8; i++) v[8 + i] = pj[i];
    v[16] = pe[0];
    v[17] = pe[1];
}

__device__ __forceinline__ void sts_tile(const float4* v, uint32_t abase, int lane) {
    uint32_t r = abase + (uint32_t)(lane >> 1) * A_STRIDE + (uint32_t)(lane & 1) * 64;
    #pragma unroll
    for (int i = 0; i < 8; i++) {
        uint32_t lo = pk(v[i].x, v[i].y), hi = pk(v[i].z, v[i].w);
        asm volatile("st.shared.v2.b32 [%0], {%1,%2};" :: "r"(r + i * 8), "r"(lo), "r"(hi));
    }
    #pragma unroll
    for (int i = 0; i < 8; i++) {
        uint32_t lo = pk(v[8 + i].x, v[8 + i].y), hi = pk(v[8 + i].z, v[8 + i].w);
        asm volatile("st.shared.v2.b32 [%0], {%1,%2};" :: "r"(r + 128 + i * 8), "r"(lo), "r"(hi));
    }
    uint32_t re = abase + (uint32_t)(lane >> 1) * A_STRIDE + 256 + (uint32_t)(lane & 1) * 16;
    #pragma unroll
    for (int i = 0; i < 2; i++) {
        uint32_t lo = pk(v[16 + i].x, v[16 + i].y), hi = pk(v[16 + i].z, v[16 + i].w);
        asm volatile("st.shared.v2.b32 [%0], {%1,%2};" :: "r"(re + i * 8), "r"(lo), "r"(hi));
    }
}

// ---------------------------------------------------------------- setup kernel
// fp32 W1[k][n]/W2[k][n] -> fp16 SAME [k][n] layout, padded strides, in g_wh.
__global__ void convert_weights_kernel(const float* __restrict__ W1,
                                       const float* __restrict__ W2) {
    int idx = blockIdx.x * blockDim.x + threadIdx.x;
    if (idx < DIN * HID) {
        int k = idx >> 7, n = idx & 127;
        *(__half*)(g_wh + OFF_W1 + k * W1_STRIDE + n * 2) = __float2half(W1[idx]);
    } else {
        int j = idx - DIN * HID;
        if (j < HID * C_DIM) {
            int k = j >> 6, n = j & 63;
            *(__half*)(g_wh + OFF_W2 + k * W2_STRIDE + n * 2) = __float2half(W2[j]);
        }
    }
}

// ---------------------------------------------------------------- main kernel
__global__ void __launch_bounds__(256, 2)
message_pass_kernel(const float* __restrict__ x_i,
                    const float* __restrict__ x_j,
                    const float* __restrict__ edge_attr,
                    const float* __restrict__ b1,
                    const float* __restrict__ b2,
                    const float* __restrict__ alphaP,
                    float* __restrict__ out,
                    int E) {
    extern __shared__ char smem[];
    const uint32_t sb = smem_u32(smem);
    const int tid = threadIdx.x;
    const int lane = tid & 31;
    const int w = tid >> 5;
    const int t = (int)blockIdx.x;

    // my tile's gmem loads first (overlap the weight copy)
    float4 v[18];
    ldg_tile(v, t, E, w, lane, x_i, x_j, edge_attr);

    // copy ready fp16 weight image scratch -> smem (57.6 KB, float4)
    {
        const float4* src = (const float4*)g_wh;
        float4* dst = (float4*)smem;
        for (int i = tid; i < WBYTES / 16; i += 256) dst[i] = src[i];
    }
    float* b1s = (float*)(smem + OFF_B1);
    float* b2s = (float*)(smem + OFF_B2);
    if (tid < HID)   b1s[tid] = b1[tid];
    if (tid < C_DIM) b2s[tid] = b2[tid];
    const float alpha = alphaP[0];
    __syncthreads();

    const uint32_t abase = sb + OFF_A + (uint32_t)w * 16 * A_STRIDE;
    sts_tile(v, abase, lane);
    __syncwarp();

    // trans-ldmatrix per-lane base for B ([k][n] rows):
    // matrix m = lane>>3: k-row = (lane&7) + 8*(m&1); +16B n-offset for m>=2.
    const uint32_t krow = (uint32_t)(lane & 7) + 8u * ((lane >> 3) & 1);
    const uint32_t noff = ((lane >> 4) & 1) * 16u;
    const uint32_t w1l = sb + OFF_W1 + krow * W1_STRIDE + noff;
    const uint32_t w2l = sb + OFF_W2 + krow * W2_STRIDE + noff;
    const int cq = (lane & 3) * 2;

    // ---- GEMM1: [16 x 144] @ W1 -> [16 x 128]  (9 k-steps, 16 n-tiles)
    float acc1[16][4];
    #pragma unroll
    for (int nt = 0; nt < 16; nt++)
        #pragma unroll
        for (int j = 0; j < 4; j++) acc1[nt][j] = 0.0f;

    #pragma unroll
    for (int kt = 0; kt < 9; kt++) {
        uint32_t a[4];
        lda(a, abase, lane, kt);
        uint32_t B[32];
        #pragma unroll
        for (int q = 0; q < 8; q++)
            ldb4(B + 4 * q, w1l + (uint32_t)(kt * 16) * W1_STRIDE + (uint32_t)(q * 32));
        #pragma unroll
        for (int q = 0; q < 8; q++) {
            mma16816(acc1[2 * q + 0], a, B[4 * q + 0], B[4 * q + 1]);
            mma16816(acc1[2 * q + 1], a, B[4 * q + 2], B[4 * q + 3]);
        }
    }

    // ---- epilogue1: h = prelu(acc1 + b1) -> fp16 A-fragments for GEMM2
    uint32_t af[8][4];
    #pragma unroll
    for (int p = 0; p < 8; p++) {
        #pragma unroll
        for (int hh = 0; hh < 2; hh++) {
            int nt = 2 * p + hh;
            float bb0 = b1s[8 * nt + cq], bb1 = b1s[8 * nt + cq + 1];
            float h0 = acc1[nt][0] + bb0; h0 = (h0 >= 0.0f) ? h0 : alpha * h0;
            float h1 = acc1[nt][1] + bb1; h1 = (h1 >= 0.0f) ? h1 : alpha * h1;
            float h2 = acc1[nt][2] + bb0; h2 = (h2 >= 0.0f) ? h2 : alpha * h2;
            float h3 = acc1[nt][3] + bb1; h3 = (h3 >= 0.0f) ? h3 : alpha * h3;
            af[p][2 * hh + 0] = pk(h0, h1);
            af[p][2 * hh + 1] = pk(h2, h3);
        }
    }

    // ---- GEMM2: [16 x 128] @ W2 -> [16 x 64]  (8 k-steps, 8 n-tiles)
    float acc2[8][4];
    #pragma unroll
    for (int nt = 0; nt < 8; nt++)
        #pragma unroll
        for (int j = 0; j < 4; j++) acc2[nt][j] = 0.0f;

    #pragma unroll
    for (int kt2 = 0; kt2 < 8; kt2++) {
        uint32_t B[16];
        #pragma unroll
        for (int q = 0; q < 4; q++)
            ldb4(B + 4 * q, w2l + (uint32_t)(kt2 * 16) * W2_STRIDE + (uint32_t)(q * 32));
        #pragma unroll
        for (int q = 0; q < 4; q++) {
            mma16816(acc2[2 * q + 0], af[kt2], B[4 * q + 0], B[4 * q + 1]);
            mma16816(acc2[2 * q + 1], af[kt2], B[4 * q + 2], B[4 * q + 3]);
        }
    }

    // ---- epilogue2: out = prelu(acc2 + b2), float2 stores
    {
        int r0 = t * TILE_M + w * 16 + (lane >> 2);
        #pragma unroll
        for (int nt2 = 0; nt2 < 8; nt2++) {
            int c = 8 * nt2 + cq;
            float bb0 = b2s[c], bb1 = b2s[c + 1];
            float o0 = acc2[nt2][0] + bb0; o0 = (o0 >= 0.0f) ? o0 : alpha * o0;
            float o1 = acc2[nt2][1] + bb1; o1 = (o1 >= 0.0f) ? o1 : alpha * o1;
            float o2 = acc2[nt2][2] + bb0; o2 = (o2 >= 0.0f) ? o2 : alpha * o2;
            float o3 = acc2[nt2][3] + bb1; o3 = (o3 >= 0.0f) ? o3 : alpha * o3;
            if (r0 < E)
                *(float2*)(out + (size_t)r0 * C_DIM + c) = make_float2(o0, o1);
            if (r0 + 8 < E)
                *(float2*)(out + (size_t)(r0 + 8) * C_DIM + c) = make_float2(o2, o3);
        }
    }
}

// ---------------------------------------------------------------- launch
extern "C" void kernel_launch(void* const* d_in, const int* in_sizes, int n_in,
                              void* d_out, int out_size) {
    const float* x_i    = (const float*)d_in[0];
    const float* x_j    = (const float*)d_in[1];
    const float* edge_a = (const float*)d_in[2];
    const float* W1     = (const float*)d_in[3];
    const float* b1     = (const float*)d_in[4];
    const float* W2     = (const float*)d_in[5];
    const float* b2     = (const float*)d_in[6];
    const float* alphaP = (const float*)d_in[7];
    float* out = (float*)d_out;

    int E = in_sizes[0] / C_DIM;
    int ntiles = (E + TILE_M - 1) / TILE_M;
    if (ntiles < 1) ntiles = 1;

    convert_weights_kernel<<<(DIN * HID + HID * C_DIM + 255) / 256, 256>>>(W1, W2);

    cudaFuncSetAttribute(message_pass_kernel,
                         cudaFuncAttributeMaxDynamicSharedMemorySize, SMEM_TOTAL);
    message_pass_kernel<<<ntiles, 256, SMEM_TOTAL>>>(
        x_i, x_j, edge_a, b1, b2, alphaP, out, E);
}

// round 17
// speedup vs baseline: 1.1499x; 1.1368x over previous
#include <cuda_runtime.h>
#include <cuda_fp16.h>
#include <cstdint>

// ----------------------------------------------------------------------------
// message_pass: out = prelu(prelu([x_i|x_j|edge] @ W1 + b1) @ W2 + b2)
// E=500000, C=64, CE=16, d_in=144, HID=128
//
// R17 == R16 (never ran): B-fragment DATA reuse (R15 post-mortem: L1 is
// wavefront/data-bound, not instruction-bound). 4 warps x 32 rows each
// (was 8 x 16): every B fragment feeds 2 mmas => smem read volume per tile
// 464KB -> ~250KB. 128 threads/CTA, occupancy 2, register-fused pipeline.
// ----------------------------------------------------------------------------

#define C_DIM   64
#define CE_DIM  16
#define DIN     144
#define HID     128
#define TILE_M  128

// strides in bytes
#define W1_STRIDE 272   // [k][n] fp16, 128 used / 136 padded
#define W2_STRIDE 144   // [k][n] fp16, 64 used / 72 padded
#define A_STRIDE  304   // 144 fp16 used / 152 padded (R9-validated)

// weight image layout (same in scratch and smem): rows = k, cols = n
#define OFF_W1 0                     // 144 * 272 = 39168
#define OFF_W2 39168                 // 128 * 144 = 18432
#define WBYTES 57600
// smem-only regions
#define OFF_B1 57600                 // 128 floats
#define OFF_B2 58112                 // 64 floats
#define OFF_A  58368                 // 4 warps * 32 rows * 304 = 38912
#define SMEM_TOTAL 97280

#define NTHREADS 128

__device__ __align__(16) unsigned char g_wh[WBYTES];   // fp16 weight scratch

// ---------------------------------------------------------------- helpers
__device__ __forceinline__ uint32_t smem_u32(const void* p) {
    uint32_t a;
    asm("{ .reg .u64 t; cvta.to.shared.u64 t, %1; cvt.u32.u64 %0, t; }" : "=r"(a) : "l"(p));
    return a;
}

__device__ __forceinline__ uint32_t pk(float lo, float hi) {
    __half2 h = __floats2half2_rn(lo, hi);
    return *reinterpret_cast<uint32_t*>(&h);
}

__device__ __forceinline__ void mma16816(float* d, const uint32_t* a,
                                         uint32_t b0, uint32_t b1) {
    asm volatile(
        "mma.sync.aligned.m16n8k16.row.col.f32.f16.f16.f32 "
        "{%0,%1,%2,%3}, {%4,%5,%6,%7}, {%8,%9}, {%0,%1,%2,%3};"
        : "+f"(d[0]), "+f"(d[1]), "+f"(d[2]), "+f"(d[3])
        : "r"(a[0]), "r"(a[1]), "r"(a[2]), "r"(a[3]), "r"(b0), "r"(b1));
}

// A fragment via ldmatrix.x4 (non-trans); mbase = start of a 16-row block.
__device__ __forceinline__ void lda(uint32_t* a, uint32_t mbase, int lane, int kt) {
    int m = lane >> 3;
    uint32_t addr = mbase
                  + (uint32_t)((lane & 7) + 8 * (m & 1)) * A_STRIDE
                  + (uint32_t)(16 * (m >> 1))
                  + (uint32_t)(kt * 32);
    asm volatile("ldmatrix.sync.aligned.m8n8.x4.shared.b16 {%0,%1,%2,%3}, [%4];"
        : "=r"(a[0]), "=r"(a[1]), "=r"(a[2]), "=r"(a[3]) : "r"(addr));
}

// B fragments via ldmatrix.x4.trans from [k][n] storage (rows = k):
//   m0=(k0-7,n0-7)->b0 of n-tile 2q   m1=(k8-15,n0-7)->b1 of n-tile 2q
//   m2=(k0-7,n8-15)->b0 of 2q+1      m3=(k8-15,n8-15)->b1 of 2q+1
__device__ __forceinline__ void ldb4(uint32_t* b, uint32_t addr) {
    asm volatile("ldmatrix.sync.aligned.m8n8.x4.trans.shared.b16 {%0,%1,%2,%3}, [%4];"
        : "=r"(b[0]), "=r"(b[1]), "=r"(b[2]), "=r"(b[3]) : "r"(addr));
}

// ---------------------------------------------------------------- tile I/O
// 16 rows per call: 2 lanes per row, 18 float4 per lane. h16 = 0/1 selects
// which 16-row half of the warp's 32-row stripe.
__device__ __forceinline__ void ldg_tile(float4* v, int t, int E, int w, int h16,
                                         int lane,
                                         const float* __restrict__ xi,
                                         const float* __restrict__ xj,
                                         const float* __restrict__ ea) {
    int row = t * TILE_M + w * 32 + h16 * 16 + (lane >> 1);
    size_t rc = (size_t)(row < E ? row : E - 1);
    int half = lane & 1;
    const float4* pi = (const float4*)(xi + rc * C_DIM) + half * 8;
    const float4* pj = (const float4*)(xj + rc * C_DIM) + half * 8;
    const float4* pe = (const float4*)(ea + rc * CE_DIM) + half * 2;
    #pragma unroll
    for (int i = 0; i < 8; i++) v[i] = pi[i];
    #pragma unroll
    for (int i = 0; i < 8; i++) v[8 + i] = pj[i];
    v[16] = pe[0];
    v[17] = pe[1];
}

__device__ __forceinline__ void sts_tile(const float4* v, uint32_t base16, int lane) {
    uint32_t r = base16 + (uint32_t)(lane >> 1) * A_STRIDE + (uint32_t)(lane & 1) * 64;
    #pragma unroll
    for (int i = 0; i < 8; i++) {
        uint32_t lo = pk(v[i].x, v[i].y), hi = pk(v[i].z, v[i].w);
        asm volatile("st.shared.v2.b32 [%0], {%1,%2};" :: "r"(r + i * 8), "r"(lo), "r"(hi));
    }
    #pragma unroll
    for (int i = 0; i < 8; i++) {
        uint32_t lo = pk(v[8 + i].x, v[8 + i].y), hi = pk(v[8 + i].z, v[8 + i].w);
        asm volatile("st.shared.v2.b32 [%0], {%1,%2};" :: "r"(r + 128 + i * 8), "r"(lo), "r"(hi));
    }
    uint32_t re = base16 + (uint32_t)(lane >> 1) * A_STRIDE + 256 + (uint32_t)(lane & 1) * 16;
    #pragma unroll
    for (int i = 0; i < 2; i++) {
        uint32_t lo = pk(v[16 + i].x, v[16 + i].y), hi = pk(v[16 + i].z, v[16 + i].w);
        asm volatile("st.shared.v2.b32 [%0], {%1,%2};" :: "r"(re + i * 8), "r"(lo), "r"(hi));
    }
}

// ---------------------------------------------------------------- setup kernel
__global__ void convert_weights_kernel(const float* __restrict__ W1,
                                       const float* __restrict__ W2) {
    int idx = blockIdx.x * blockDim.x + threadIdx.x;
    if (idx < DIN * HID) {
        int k = idx >> 7, n = idx & 127;
        *(__half*)(g_wh + OFF_W1 + k * W1_STRIDE + n * 2) = __float2half(W1[idx]);
    } else {
        int j = idx - DIN * HID;
        if (j < HID * C_DIM) {
            int k = j >> 6, n = j & 63;
            *(__half*)(g_wh + OFF_W2 + k * W2_STRIDE + n * 2) = __float2half(W2[j]);
        }
    }
}

// ---------------------------------------------------------------- main kernel
__global__ void __launch_bounds__(NTHREADS, 2)
message_pass_kernel(const float* __restrict__ x_i,
                    const float* __restrict__ x_j,
                    const float* __restrict__ edge_attr,
                    const float* __restrict__ b1,
                    const float* __restrict__ b2,
                    const float* __restrict__ alphaP,
                    float* __restrict__ out,
                    int E) {
    extern __shared__ char smem[];
    const uint32_t sb = smem_u32(smem);
    const int tid = threadIdx.x;
    const int lane = tid & 31;
    const int w = tid >> 5;          // 4 warps, each owns 32 rows
    const int t = (int)blockIdx.x;

    // stage both 16-row halves' gmem loads first (latency under weight copy)
    float4 v1[18], v2[18];
    ldg_tile(v1, t, E, w, 0, lane, x_i, x_j, edge_attr);
    ldg_tile(v2, t, E, w, 1, lane, x_i, x_j, edge_attr);

    // copy ready fp16 weight image scratch -> smem (57.6 KB, float4)
    {
        const float4* src = (const float4*)g_wh;
        float4* dst = (float4*)smem;
        for (int i = tid; i < WBYTES / 16; i += NTHREADS) dst[i] = src[i];
    }
    float* b1s = (float*)(smem + OFF_B1);
    float* b2s = (float*)(smem + OFF_B2);
    if (tid < HID) b1s[tid] = b1[tid];
    if (tid < C_DIM) b2s[tid] = b2[tid];
    const float alpha = alphaP[0];

    const uint32_t abase = sb + OFF_A + (uint32_t)w * 32 * A_STRIDE;   // rows w*32..
    const uint32_t abase_hi = abase + 16 * A_STRIDE;
    sts_tile(v1, abase, lane);
    sts_tile(v2, abase_hi, lane);
    __syncthreads();   // weights + biases visible; stripe is warp-private anyway

    // trans-ldmatrix per-lane base for B ([k][n] rows)
    const uint32_t krow = (uint32_t)(lane & 7) + 8u * ((lane >> 3) & 1);
    const uint32_t noff = ((lane >> 4) & 1) * 16u;
    const uint32_t w1l = sb + OFF_W1 + krow * W1_STRIDE + noff;
    const uint32_t w2l = sb + OFF_W2 + krow * W2_STRIDE + noff;
    const int cq = (lane & 3) * 2;

    // ---- GEMM1: [32 x 144] @ W1 -> [32 x 128]  (9 k-steps, 16 n-tiles)
    // lo = rows 0-15 of stripe, hi = rows 16-31. Each B frag feeds 2 mmas.
    float acc1a[16][4], acc1b[16][4];
    #pragma unroll
    for (int nt = 0; nt < 16; nt++)
        #pragma unroll
        for (int j = 0; j < 4; j++) { acc1a[nt][j] = 0.0f; acc1b[nt][j] = 0.0f; }

    #pragma unroll
    for (int kt = 0; kt < 9; kt++) {
        uint32_t alo[4], ahi[4];
        lda(alo, abase, lane, kt);
        lda(ahi, abase_hi, lane, kt);
        uint32_t B[32];
        #pragma unroll
        for (int q = 0; q < 8; q++)
            ldb4(B + 4 * q, w1l + (uint32_t)(kt * 16) * W1_STRIDE + (uint32_t)(q * 32));
        #pragma unroll
        for (int q = 0; q < 8; q++) {
            mma16816(acc1a[2 * q + 0], alo, B[4 * q + 0], B[4 * q + 1]);
            mma16816(acc1a[2 * q + 1], alo, B[4 * q + 2], B[4 * q + 3]);
            mma16816(acc1b[2 * q + 0], ahi, B[4 * q + 0], B[4 * q + 1]);
            mma16816(acc1b[2 * q + 1], ahi, B[4 * q + 2], B[4 * q + 3]);
        }
    }

    // ---- epilogue1: h = prelu(acc1 + b1) -> fp16 A-fragments for GEMM2
    uint32_t afa[8][4], afb[8][4];
    #pragma unroll
    for (int p = 0; p < 8; p++) {
        #pragma unroll
        for (int hh = 0; hh < 2; hh++) {
            int nt = 2 * p + hh;
            float bb0 = b1s[8 * nt + cq], bb1 = b1s[8 * nt + cq + 1];
            float h0 = acc1a[nt][0] + bb0; h0 = (h0 >= 0.0f) ? h0 : alpha * h0;
            float h1 = acc1a[nt][1] + bb1; h1 = (h1 >= 0.0f) ? h1 : alpha * h1;
            float h2 = acc1a[nt][2] + bb0; h2 = (h2 >= 0.0f) ? h2 : alpha * h2;
            float h3 = acc1a[nt][3] + bb1; h3 = (h3 >= 0.0f) ? h3 : alpha * h3;
            afa[p][2 * hh + 0] = pk(h0, h1);
            afa[p][2 * hh + 1] = pk(h2, h3);
            float g0 = acc1b[nt][0] + bb0; g0 = (g0 >= 0.0f) ? g0 : alpha * g0;
            float g1 = acc1b[nt][1] + bb1; g1 = (g1 >= 0.0f) ? g1 : alpha * g1;
            float g2 = acc1b[nt][2] + bb0; g2 = (g2 >= 0.0f) ? g2 : alpha * g2;
            float g3 = acc1b[nt][3] + bb1; g3 = (g3 >= 0.0f) ? g3 : alpha * g3;
            afb[p][2 * hh + 0] = pk(g0, g1);
            afb[p][2 * hh + 1] = pk(g2, g3);
        }
    }

    // ---- GEMM2: [32 x 128] @ W2 -> [32 x 64]  (8 k-steps, 8 n-tiles)
    float acc2a[8][4], acc2b[8][4];
    #pragma unroll
    for (int nt = 0; nt < 8; nt++)
        #pragma unroll
        for (int j = 0; j < 4; j++) { acc2a[nt][j] = 0.0f; acc2b[nt][j] = 0.0f; }

    #pragma unroll
    for (int kt2 = 0; kt2 < 8; kt2++) {
        uint32_t B[16];
        #pragma unroll
        for (int q = 0; q < 4; q++)
            ldb4(B + 4 * q, w2l + (uint32_t)(kt2 * 16) * W2_STRIDE + (uint32_t)(q * 32));
        #pragma unroll
        for (int q = 0; q < 4; q++) {
            mma16816(acc2a[2 * q + 0], afa[kt2], B[4 * q + 0], B[4 * q + 1]);
            mma16816(acc2a[2 * q + 1], afa[kt2], B[4 * q + 2], B[4 * q + 3]);
            mma16816(acc2b[2 * q + 0], afb[kt2], B[4 * q + 0], B[4 * q + 1]);
            mma16816(acc2b[2 * q + 1], afb[kt2], B[4 * q + 2], B[4 * q + 3]);
        }
    }

    // ---- epilogue2: out = prelu(acc2 + b2), float2 stores (4 rows per lane)
    {
        int r0 = t * TILE_M + w * 32 + (lane >> 2);
        #pragma unroll
        for (int nt2 = 0; nt2 < 8; nt2++) {
            int c = 8 * nt2 + cq;
            float bb0 = b2s[c], bb1 = b2s[c + 1];
            float o0 = acc2a[nt2][0] + bb0; o0 = (o0 >= 0.0f) ? o0 : alpha * o0;
            float o1 = acc2a[nt2][1] + bb1; o1 = (o1 >= 0.0f) ? o1 : alpha * o1;
            float o2 = acc2a[nt2][2] + bb0; o2 = (o2 >= 0.0f) ? o2 : alpha * o2;
            float o3 = acc2a[nt2][3] + bb1; o3 = (o3 >= 0.0f) ? o3 : alpha * o3;
            float p0 = acc2b[nt2][0] + bb0; p0 = (p0 >= 0.0f) ? p0 : alpha * p0;
            float p1 = acc2b[nt2][1] + bb1; p1 = (p1 >= 0.0f) ? p1 : alpha * p1;
            float p2 = acc2b[nt2][2] + bb0; p2 = (p2 >= 0.0f) ? p2 : alpha * p2;
            float p3 = acc2b[nt2][3] + bb1; p3 = (p3 >= 0.0f) ? p3 : alpha * p3;
            if (r0 < E)
                *(float2*)(out + (size_t)r0 * C_DIM + c) = make_float2(o0, o1);
            if (r0 + 8 < E)
                *(float2*)(out + (size_t)(r0 + 8) * C_DIM + c) = make_float2(o2, o3);
            if (r0 + 16 < E)
                *(float2*)(out + (size_t)(r0 + 16) * C_DIM + c) = make_float2(p0, p1);
            if (r0 + 24 < E)
                *(float2*)(out + (size_t)(r0 + 24) * C_DIM + c) = make_float2(p2, p3);
        }
    }
}

// ---------------------------------------------------------------- launch
extern "C" void kernel_launch(void* const* d_in, const int* in_sizes, int n_in,
                              void* d_out, int out_size) {
    const float* x_i    = (const float*)d_in[0];
    const float* x_j    = (const float*)d_in[1];
    const float* edge_a = (const float*)d_in[2];
    const float* W1     = (const float*)d_in[3];
    const float* b1     = (const float*)d_in[4];
    const float* W2     = (const float*)d_in[5];
    const float* b2     = (const float*)d_in[6];
    const float* alphaP = (const float*)d_in[7];
    float* out = (float*)d_out;

    int E = in_sizes[0] / C_DIM;
    int ntiles = (E + TILE_M - 1) / TILE_M;
    if (ntiles < 1) ntiles = 1;

    convert_weights_kernel<<<(DIN * HID + HID * C_DIM + 255) / 256, 256>>>(W1, W2);

    cudaFuncSetAttribute(message_pass_kernel,
                         cudaFuncAttributeMaxDynamicSharedMemorySize, SMEM_TOTAL);
    message_pass_kernel<<<ntiles, NTHREADS, SMEM_TOTAL>>>(
        x_i, x_j, edge_a, b1, b2, alphaP, out, E);
}